// round 16
// baseline (speedup 1.0000x reference)
#include <cuda_runtime.h>
#include <cuda_fp16.h>

#define NN 100000
#define NE 1600000
#define DIM 128

#define SCAN_B 512
#define SCAN_NBLK ((NN + SCAN_B - 1) / SCAN_B)   // 196

// split point for agg1/gemm2 pipeline (multiple of 128)
#define NA 50048

typedef unsigned long long u64;

// ---------------- scratch (static device memory; no allocs) ----------------
__device__ __align__(16) float  g_deg[NN];     // 1 + sum(ew-1) during hist
__device__ __align__(16) float  g_dinv[NN];
__device__ __align__(16) int    g_cnt[NN];
__device__ __align__(16) int    g_off[NN];
__device__ __align__(16) int    g_cursor[NN];
__device__ __align__(16) int2   g_edge[NE];               // (src row, norm as int bits)
__device__ __align__(16) __half g_h[(size_t)NN * DIM];    // layer-1 pre-agg (x @ W1), fp16
__device__ __align__(16) __half g_h2[(size_t)NN * DIM];   // layer-2 pre-agg (z @ W2), fp16
__device__ __align__(16) __half g_z16[(size_t)NN * DIM];  // layer-1 output, fp16
__device__ __align__(16) int    g_bsum[SCAN_NBLK];
__device__ int g_is64;                                    // edge_index dtype flag

// ---------------- init (+ parallel edge dtype detect) ----------------
// int64 little-endian values < 2^31: every odd 32-bit word is 0.
__global__ void k_init(const int* __restrict__ ei32) {
    int i = blockIdx.x * blockDim.x + threadIdx.x;
    if (i < NN) { g_deg[i] = 1.0f; g_cnt[i] = 0; }   // self-loop weight 1
    if (blockIdx.x == 0) {
        __shared__ unsigned w[2];
        int t = threadIdx.x;
        if (t < 64) {
            int nz = (ei32[2 * t + 1] != 0);
            unsigned b = __ballot_sync(0xffffffffu, nz);
            if ((t & 31) == 0) w[t >> 5] = b;
        }
        __syncthreads();
        if (t == 0) g_is64 = ((w[0] | w[1]) == 0u) ? 1 : 0;
    }
}

// ---------------- degree / histogram (2 edges per thread) ----------------
// deg = 1 + sum(ew). Int atomic counts edges; float atomic fires only for
// ew != 1 (never for unit weights). scan1 reconstructs deg = g_deg + cnt.
__global__ void k_hist(const void* __restrict__ ei, const float* __restrict__ ew) {
    int p = blockIdx.x * blockDim.x + threadIdx.x;   // pair index
    int e = p * 2;
    if (e >= NE) return;
    int is64 = g_is64;
    int c0, c1;
    if (is64) {
        longlong2 cc = *(const longlong2*)&((const long long*)ei)[(size_t)NE + e];
        c0 = (int)cc.x; c1 = (int)cc.y;
    } else {
        int2 cc = *(const int2*)&((const int*)ei)[(size_t)NE + e];
        c0 = cc.x; c1 = cc.y;
    }
    float2 ww = *(const float2*)&ew[e];
    if ((unsigned)c0 < NN) {
        atomicAdd(&g_cnt[c0], 1);
        if (ww.x != 1.0f) atomicAdd(&g_deg[c0], ww.x - 1.0f);
    }
    if ((unsigned)c1 < NN) {
        atomicAdd(&g_cnt[c1], 1);
        if (ww.y != 1.0f) atomicAdd(&g_deg[c1], ww.y - 1.0f);
    }
}

// ---------------- scan phase 1 (+ dinv fused) ----------------
__global__ void k_scan1() {
    __shared__ int s[SCAN_B];
    int i = blockIdx.x * SCAN_B + threadIdx.x;
    int cnt = (i < NN) ? g_cnt[i] : 0;
    s[threadIdx.x] = cnt;
    if (i < NN) {
        float d = g_deg[i] + (float)cnt;
        g_dinv[i] = (d > 0.0f) ? rsqrtf(d) : 0.0f;
    }
    __syncthreads();
    for (int st = SCAN_B / 2; st > 0; st >>= 1) {
        if ((int)threadIdx.x < st) s[threadIdx.x] += s[threadIdx.x + st];
        __syncthreads();
    }
    if (threadIdx.x == 0) g_bsum[blockIdx.x] = s[0];
}

// ---------------- scan phase 2: per-block base computed in-block ----------
__global__ void k_scan3() {
    __shared__ int s[SCAN_B];
    __shared__ int sb[256];
    __shared__ int s_base;

    int t = threadIdx.x;
    if (t < 256) {
        sb[t] = (t < (int)blockIdx.x && t < SCAN_NBLK) ? g_bsum[t] : 0;
    }
    int i = blockIdx.x * SCAN_B + t;
    int v = (i < NN) ? g_cnt[i] : 0;
    s[t] = v;
    __syncthreads();
    if (t < 128) sb[t] += sb[t + 128];
    __syncthreads();
    if (t < 64) sb[t] += sb[t + 64];
    __syncthreads();
    if (t < 32) {
        int x = sb[t] + sb[t + 32];
        #pragma unroll
        for (int o = 16; o > 0; o >>= 1) x += __shfl_down_sync(0xffffffff, x, o);
        if (t == 0) s_base = x;
    }
    for (int st = 1; st < SCAN_B; st <<= 1) {
        int u = 0;
        if (t >= st) u = s[t - st];
        __syncthreads();
        if (t >= st) s[t] += u;
        __syncthreads();
    }
    if (i < NN) {
        int excl = s_base + s[t] - v;
        g_off[i]    = excl;
        g_cursor[i] = excl;
    }
}

// ---------------- bucket edges by destination (2 edges per thread) --------
__global__ void k_scatter(const void* __restrict__ ei, const float* __restrict__ ew) {
    int p = blockIdx.x * blockDim.x + threadIdx.x;
    int e = p * 2;
    if (e >= NE) return;
    int is64 = g_is64;
    int r0, r1, c0, c1;
    if (is64) {
        longlong2 rr = *(const longlong2*)&((const long long*)ei)[e];
        longlong2 cc = *(const longlong2*)&((const long long*)ei)[(size_t)NE + e];
        r0 = (int)rr.x; r1 = (int)rr.y; c0 = (int)cc.x; c1 = (int)cc.y;
    } else {
        int2 rr = *(const int2*)&((const int*)ei)[e];
        int2 cc = *(const int2*)&((const int*)ei)[(size_t)NE + e];
        r0 = rr.x; r1 = rr.y; c0 = cc.x; c1 = cc.y;
    }
    float2 ww = *(const float2*)&ew[e];
    if ((unsigned)r0 < NN && (unsigned)c0 < NN) {
        int pos = atomicAdd(&g_cursor[c0], 1);
        g_edge[pos] = make_int2(r0, __float_as_int(g_dinv[r0] * ww.x * g_dinv[c0]));
    }
    if ((unsigned)r1 < NN && (unsigned)c1 < NN) {
        int pos = atomicAdd(&g_cursor[c1], 1);
        g_edge[pos] = make_int2(r1, __float_as_int(g_dinv[r1] * ww.y * g_dinv[c1]));
    }
}

// ---------------- tensor-core GEMM: H(fp16) = A[rows,128] @ W[128,128] -----
// mma.sync m16n8k16 f16/f32. 256 threads = 8 warps, warp owns m16 x n128.
// FROM_GZ=false: A = x (fp32 param). FROM_GZ=true: A = g_z16 (fp16 symbol).
// TO_H2: write g_h2 (layer 2) instead of g_h (layer 1) — breaks the
// WAR hazard between gemm2 and the concurrent agg1 gather over g_h.
#define GEMM_BM 128

__device__ __forceinline__ void mma16816(float* c, unsigned a0, unsigned a1,
                                         unsigned a2, unsigned a3,
                                         unsigned b0, unsigned b1) {
    asm volatile(
        "mma.sync.aligned.m16n8k16.row.col.f32.f16.f16.f32 "
        "{%0,%1,%2,%3}, {%4,%5,%6,%7}, {%8,%9}, {%0,%1,%2,%3};"
        : "+f"(c[0]), "+f"(c[1]), "+f"(c[2]), "+f"(c[3])
        : "r"(a0), "r"(a1), "r"(a2), "r"(a3), "r"(b0), "r"(b1));
}

template<bool FROM_GZ, bool TO_H2>
__global__ __launch_bounds__(256) void k_gemm(const float* __restrict__ Ain,
                                              const float* __restrict__ W,
                                              int rowStart) {
    __half* Hout = TO_H2 ? g_h2 : g_h;

    __shared__ __half Ws[128][136];   // full W, k-major rows, padded
    __shared__ __half As[128][40];    // one k=32 chunk of A, padded

    int tid  = threadIdx.x;
    int wid  = tid >> 5;
    int lane = tid & 31;
    int rowBase = rowStart + blockIdx.x * GEMM_BM;
    int m_base  = wid * 16;

    // Load + convert W (4096 float4 = 16384 floats)
    for (int i = tid; i < 4096; i += 256) {
        int r = i >> 5;
        int c = (i & 31) * 4;
        float4 w4 = *(const float4*)&W[r * DIM + c];
        *(__half2*)&Ws[r][c]     = __floats2half2_rn(w4.x, w4.y);
        *(__half2*)&Ws[r][c + 2] = __floats2half2_rn(w4.z, w4.w);
    }

    float acc[16][4];
    #pragma unroll
    for (int i = 0; i < 16; i++)
        #pragma unroll
        for (int j = 0; j < 4; j++) acc[i][j] = 0.0f;

    for (int kc = 0; kc < 4; kc++) {
        int k0g = kc * 32;
        __syncthreads();             // As reuse fence (covers Ws on iter 0)
        if (FROM_GZ) {
            for (int i = tid; i < 512; i += 256) {
                int r = i >> 2;
                int c = (i & 3) * 8;
                int grow = rowBase + r;
                uint4 v = make_uint4(0u, 0u, 0u, 0u);
                if (grow < NN) v = *(const uint4*)&g_z16[(size_t)grow * DIM + k0g + c];
                *(uint4*)&As[r][c] = v;
            }
        } else {
            for (int i = tid; i < 1024; i += 256) {
                int r = i >> 3;
                int c = (i & 7) * 4;
                int grow = rowBase + r;
                float4 a4 = (grow < NN)
                    ? *(const float4*)&Ain[(size_t)grow * DIM + k0g + c]
                    : make_float4(0.f, 0.f, 0.f, 0.f);
                *(__half2*)&As[r][c]     = __floats2half2_rn(a4.x, a4.y);
                *(__half2*)&As[r][c + 2] = __floats2half2_rn(a4.z, a4.w);
            }
        }
        __syncthreads();

        #pragma unroll
        for (int ks = 0; ks < 2; ks++) {
            int k0 = ks * 16;
            int kg = k0g + k0;
            unsigned a0, a1, a2, a3;
            {
                unsigned addr = (unsigned)__cvta_generic_to_shared(
                    &As[m_base + (lane & 15)][k0 + ((lane >> 4) << 3)]);
                asm volatile("ldmatrix.sync.aligned.m8n8.x4.shared.b16 "
                             "{%0,%1,%2,%3}, [%4];"
                             : "=r"(a0), "=r"(a1), "=r"(a2), "=r"(a3) : "r"(addr));
            }
            #pragma unroll
            for (int nt = 0; nt < 8; nt++) {
                int n0 = nt * 16;
                unsigned b0, b1, b2, b3;
                unsigned addr = (unsigned)__cvta_generic_to_shared(
                    &Ws[kg + (lane & 15)][n0 + ((lane >> 4) << 3)]);
                asm volatile("ldmatrix.sync.aligned.m8n8.x4.trans.shared.b16 "
                             "{%0,%1,%2,%3}, [%4];"
                             : "=r"(b0), "=r"(b1), "=r"(b2), "=r"(b3) : "r"(addr));
                mma16816(acc[2 * nt],     a0, a1, a2, a3, b0, b1);
                mma16816(acc[2 * nt + 1], a0, a1, a2, a3, b2, b3);
            }
        }
    }

    // Epilogue: fp16 half2 stores
    int gq = lane >> 2, tg = lane & 3;
    int r0 = rowBase + m_base + gq;
    int r1 = r0 + 8;
    #pragma unroll
    for (int t8 = 0; t8 < 16; t8++) {
        int n0 = t8 * 8 + 2 * tg;
        if (r0 < NN) *(__half2*)&Hout[(size_t)r0 * DIM + n0] =
            __floats2half2_rn(acc[t8][0], acc[t8][1]);
        if (r1 < NN) *(__half2*)&Hout[(size_t)r1 * DIM + n0] =
            __floats2half2_rn(acc[t8][2], acc[t8][3]);
    }
}

// ---------------- aggregation: one warp per node, unroll-4 ----------------
// FROM_H2: gather from g_h2 (layer 2) instead of g_h (layer 1).
__device__ __forceinline__ void gather_fma(float4 &acc, float n, uint2 raw) {
    float2 f01 = __half22float2(*(__half2*)&raw.x);
    float2 f23 = __half22float2(*(__half2*)&raw.y);
    acc.x += n * f01.x; acc.y += n * f01.y;
    acc.z += n * f23.x; acc.w += n * f23.y;
}

template<bool TO_OUT, bool FROM_H2>
__global__ __launch_bounds__(128) void k_agg(const float* __restrict__ bias,
                                             float* __restrict__ outp,
                                             int nodeStart, int nodeLim) {
    const __half* H = FROM_H2 ? g_h2 : g_h;

    int node = nodeStart + ((blockIdx.x * blockDim.x + threadIdx.x) >> 5);
    int lane = threadIdx.x & 31;
    if (node >= nodeLim) return;

    float di = g_dinv[node];
    float sn = di * di;              // self-loop norm (weight 1)

    const uint2* hrow = (const uint2*)(H + (size_t)node * DIM);
    float4 acc = make_float4(0.f, 0.f, 0.f, 0.f);
    gather_fma(acc, sn, hrow[lane]);

    int start = g_off[node];
    int cnt   = g_cnt[node];

    int e = 0;
    for (; e + 4 <= cnt; e += 4) {
        int2 E0 = g_edge[start + e];
        int2 E1 = g_edge[start + e + 1];
        int2 E2 = g_edge[start + e + 2];
        int2 E3 = g_edge[start + e + 3];
        uint2 V0 = ((const uint2*)(H + (size_t)E0.x * DIM))[lane];
        uint2 V1 = ((const uint2*)(H + (size_t)E1.x * DIM))[lane];
        uint2 V2 = ((const uint2*)(H + (size_t)E2.x * DIM))[lane];
        uint2 V3 = ((const uint2*)(H + (size_t)E3.x * DIM))[lane];
        gather_fma(acc, __int_as_float(E0.y), V0);
        gather_fma(acc, __int_as_float(E1.y), V1);
        gather_fma(acc, __int_as_float(E2.y), V2);
        gather_fma(acc, __int_as_float(E3.y), V3);
    }
    for (; e < cnt; e++) {
        int2 E0 = g_edge[start + e];
        uint2 V0 = ((const uint2*)(H + (size_t)E0.x * DIM))[lane];
        gather_fma(acc, __int_as_float(E0.y), V0);
    }

    float4 bb = ((const float4*)bias)[lane];
    acc.x = fmaxf(acc.x + bb.x, 0.0f);
    acc.y = fmaxf(acc.y + bb.y, 0.0f);
    acc.z = fmaxf(acc.z + bb.z, 0.0f);
    acc.w = fmaxf(acc.w + bb.w, 0.0f);

    if (TO_OUT) {
        ((float4*)outp)[(size_t)node * 32 + lane] = acc;
    } else {
        // fp16 store — numerically identical to fp32 store + fp16 load in gemm2
        __half2 p0 = __floats2half2_rn(acc.x, acc.y);
        __half2 p1 = __floats2half2_rn(acc.z, acc.w);
        uint2 v;
        v.x = *(unsigned*)&p0; v.y = *(unsigned*)&p1;
        *(uint2*)&g_z16[(size_t)node * DIM + lane * 4] = v;
    }
}

// ---------------- launch: fork-join + hazard-free split pipeline -----------
extern "C" void kernel_launch(void* const* d_in, const int* in_sizes, int n_in,
                              void* d_out, int out_size) {
    const float* x  = (const float*)d_in[0];
    const void*  ei = d_in[1];                    // int32 or int64 -> detected on device
    const float* ew = (const float*)d_in[2];
    const float* W1 = (const float*)d_in[3];
    const float* b1 = (const float*)d_in[4];
    const float* W2 = (const float*)d_in[5];
    const float* b2 = (const float*)d_in[6];
    float* out = (float*)d_out;

    const int NB = NN - NA;
    const int gemm_grid   = (NN + GEMM_BM - 1) / GEMM_BM;  // 782
    const int gemmA_grid  = NA / GEMM_BM;                  // 391
    const int gemmB_grid  = (NB + GEMM_BM - 1) / GEMM_BM;  // 391
    const int aggA_grid   = (NA * 32 + 127) / 128;
    const int aggB_grid   = (NB * 32 + 127) / 128;
    const int agg_grid    = (NN * 32 + 127) / 128;
    const int pair_grid   = (NE / 2 + 255) / 256;

    // one-time host objects (no device memory)
    static cudaStream_t s2 = nullptr;
    static cudaEvent_t  eFork = nullptr, eJoin = nullptr, eA = nullptr, eG = nullptr;
    if (!s2) {
        cudaStreamCreateWithFlags(&s2, cudaStreamNonBlocking);
        cudaEventCreateWithFlags(&eFork, cudaEventDisableTiming);
        cudaEventCreateWithFlags(&eJoin, cudaEventDisableTiming);
        cudaEventCreateWithFlags(&eA, cudaEventDisableTiming);
        cudaEventCreateWithFlags(&eG, cudaEventDisableTiming);
    }

    // fork: side stream builds CSC while main stream runs GEMM1
    cudaEventRecord(eFork, 0);
    cudaStreamWaitEvent(s2, eFork, 0);

    k_gemm<false, false><<<gemm_grid, 256>>>(x, W1, 0);   // main: x @ W1 -> g_h

    k_init<<<(NN + 255) / 256, 256, 0, s2>>>((const int*)ei);
    k_hist<<<pair_grid, 256, 0, s2>>>(ei, ew);
    k_scan1<<<SCAN_NBLK, SCAN_B, 0, s2>>>();
    k_scan3<<<SCAN_NBLK, SCAN_B, 0, s2>>>();
    k_scatter<<<pair_grid, 256, 0, s2>>>(ei, ew);

    cudaEventRecord(eJoin, s2);
    cudaStreamWaitEvent(0, eJoin, 0);

    // --- layer 1 aggregate, half A; then gemm2(A)->g_h2 overlaps agg1(B) ---
    k_agg<false, false><<<aggA_grid, 128>>>(b1, nullptr, 0, NA);

    cudaEventRecord(eA, 0);
    cudaStreamWaitEvent(s2, eA, 0);
    k_gemm<true, true><<<gemmA_grid, 256, 0, s2>>>(nullptr, W2, 0);   // z[0,NA) @ W2 -> g_h2
    cudaEventRecord(eG, s2);

    k_agg<false, false><<<aggB_grid, 128>>>(b1, nullptr, NA, NN);     // reads g_h only
    k_gemm<true, true><<<gemmB_grid, 256>>>(nullptr, W2, NA);         // z[NA,NN) @ W2 -> g_h2

    cudaStreamWaitEvent(0, eG, 0);

    // --- layer 2 aggregate (reads g_h2) -> out ---
    k_agg<true, true><<<agg_grid, 128>>>(b2, out, 0, NN);
}

// round 17
// speedup vs baseline: 1.0285x; 1.0285x over previous
#include <cuda_runtime.h>
#include <cuda_fp16.h>

#define NN 100000
#define NE 1600000
#define DIM 128

#define SCAN_B 512
#define SCAN_NBLK ((NN + SCAN_B - 1) / SCAN_B)   // 196

typedef unsigned long long u64;

// ---------------- scratch (static device memory; no allocs) ----------------
__device__ __align__(16) float  g_deg[NN];     // 1 + sum(ew-1) during hist
__device__ __align__(16) float  g_dinv[NN];
__device__ __align__(16) int    g_cnt[NN];
__device__ __align__(16) int    g_off[NN];
__device__ __align__(16) int    g_cursor[NN];
__device__ __align__(16) int2   g_edge[NE];               // (src row, norm as int bits)
__device__ __align__(16) __half g_h[(size_t)NN * DIM];    // pre-agg features, fp16
__device__ __align__(16) __half g_z16[(size_t)NN * DIM];  // layer-1 output, fp16
__device__ int g_total;                                   // CSC offset allocator
__device__ int g_is64;                                    // edge_index dtype flag

// ---------------- init (+ parallel edge dtype detect) ----------------
// int64 little-endian values < 2^31: every odd 32-bit word is 0.
__global__ void k_init(const int* __restrict__ ei32) {
    int i = blockIdx.x * blockDim.x + threadIdx.x;
    if (i < NN) { g_deg[i] = 1.0f; g_cnt[i] = 0; }   // self-loop weight 1
    if (blockIdx.x == 0) {
        __shared__ unsigned w[2];
        int t = threadIdx.x;
        if (t < 64) {
            int nz = (ei32[2 * t + 1] != 0);
            unsigned b = __ballot_sync(0xffffffffu, nz);
            if ((t & 31) == 0) w[t >> 5] = b;
        }
        __syncthreads();
        if (t == 0) {
            g_is64 = ((w[0] | w[1]) == 0u) ? 1 : 0;
            g_total = 0;
        }
    }
}

// ---------------- degree / histogram (2 edges per thread) ----------------
// deg = 1 + sum(ew). Int atomic counts edges; float atomic fires only for
// ew != 1 (never for unit weights). k_offsets reconstructs deg = g_deg + cnt.
__global__ void k_hist(const void* __restrict__ ei, const float* __restrict__ ew) {
    int p = blockIdx.x * blockDim.x + threadIdx.x;   // pair index
    int e = p * 2;
    if (e >= NE) return;
    int is64 = g_is64;
    int c0, c1;
    if (is64) {
        longlong2 cc = *(const longlong2*)&((const long long*)ei)[(size_t)NE + e];
        c0 = (int)cc.x; c1 = (int)cc.y;
    } else {
        int2 cc = *(const int2*)&((const int*)ei)[(size_t)NE + e];
        c0 = cc.x; c1 = cc.y;
    }
    float2 ww = *(const float2*)&ew[e];
    if ((unsigned)c0 < NN) {
        atomicAdd(&g_cnt[c0], 1);
        if (ww.x != 1.0f) atomicAdd(&g_deg[c0], ww.x - 1.0f);
    }
    if ((unsigned)c1 < NN) {
        atomicAdd(&g_cnt[c1], 1);
        if (ww.y != 1.0f) atomicAdd(&g_deg[c1], ww.y - 1.0f);
    }
}

// ---------------- offsets: fused dinv + single-pass scan w/ atomic base ----
// Each block scans its 512 counts, grabs a contiguous region of g_edge via
// one atomicAdd on g_total, and writes per-node offsets. Segment placement
// is run-order dependent, but each node's edge set (and thus the output)
// is unchanged.
__global__ void k_offsets() {
    __shared__ int s[SCAN_B];
    __shared__ int s_base;
    int t = threadIdx.x;
    int i = blockIdx.x * SCAN_B + t;
    int cnt = (i < NN) ? g_cnt[i] : 0;
    s[t] = cnt;
    if (i < NN) {
        float d = g_deg[i] + (float)cnt;
        g_dinv[i] = (d > 0.0f) ? rsqrtf(d) : 0.0f;
    }
    __syncthreads();
    // Hillis-Steele inclusive scan
    for (int st = 1; st < SCAN_B; st <<= 1) {
        int u = 0;
        if (t >= st) u = s[t - st];
        __syncthreads();
        if (t >= st) s[t] += u;
        __syncthreads();
    }
    if (t == SCAN_B - 1) s_base = atomicAdd(&g_total, s[t]);
    __syncthreads();
    if (i < NN) {
        int excl = s_base + s[t] - cnt;
        g_off[i]    = excl;
        g_cursor[i] = excl;
    }
}

// ---------------- bucket edges by destination (2 edges per thread) --------
__global__ void k_scatter(const void* __restrict__ ei, const float* __restrict__ ew) {
    int p = blockIdx.x * blockDim.x + threadIdx.x;
    int e = p * 2;
    if (e >= NE) return;
    int is64 = g_is64;
    int r0, r1, c0, c1;
    if (is64) {
        longlong2 rr = *(const longlong2*)&((const long long*)ei)[e];
        longlong2 cc = *(const longlong2*)&((const long long*)ei)[(size_t)NE + e];
        r0 = (int)rr.x; r1 = (int)rr.y; c0 = (int)cc.x; c1 = (int)cc.y;
    } else {
        int2 rr = *(const int2*)&((const int*)ei)[e];
        int2 cc = *(const int2*)&((const int*)ei)[(size_t)NE + e];
        r0 = rr.x; r1 = rr.y; c0 = cc.x; c1 = cc.y;
    }
    float2 ww = *(const float2*)&ew[e];
    if ((unsigned)r0 < NN && (unsigned)c0 < NN) {
        int pos = atomicAdd(&g_cursor[c0], 1);
        g_edge[pos] = make_int2(r0, __float_as_int(g_dinv[r0] * ww.x * g_dinv[c0]));
    }
    if ((unsigned)r1 < NN && (unsigned)c1 < NN) {
        int pos = atomicAdd(&g_cursor[c1], 1);
        g_edge[pos] = make_int2(r1, __float_as_int(g_dinv[r1] * ww.y * g_dinv[c1]));
    }
}

// ---------------- tensor-core GEMM: g_h(fp16) = A[NN,128] @ W[128,128] -----
// mma.sync m16n8k16 f16/f32. 256 threads = 8 warps, warp owns m16 x n128.
// FROM_GZ=false: A = x (fp32 param). FROM_GZ=true: A = g_z16 (fp16 symbol).
#define GEMM_BM 128

__device__ __forceinline__ void mma16816(float* c, unsigned a0, unsigned a1,
                                         unsigned a2, unsigned a3,
                                         unsigned b0, unsigned b1) {
    asm volatile(
        "mma.sync.aligned.m16n8k16.row.col.f32.f16.f16.f32 "
        "{%0,%1,%2,%3}, {%4,%5,%6,%7}, {%8,%9}, {%0,%1,%2,%3};"
        : "+f"(c[0]), "+f"(c[1]), "+f"(c[2]), "+f"(c[3])
        : "r"(a0), "r"(a1), "r"(a2), "r"(a3), "r"(b0), "r"(b1));
}

template<bool FROM_GZ>
__global__ __launch_bounds__(256) void k_gemm(const float* __restrict__ Ain,
                                              const float* __restrict__ W) {
    __shared__ __half Ws[128][136];   // full W, k-major rows, padded
    __shared__ __half As[128][40];    // one k=32 chunk of A, padded

    int tid  = threadIdx.x;
    int wid  = tid >> 5;
    int lane = tid & 31;
    int rowBase = blockIdx.x * GEMM_BM;
    int m_base  = wid * 16;

    // Load + convert W (4096 float4 = 16384 floats)
    for (int i = tid; i < 4096; i += 256) {
        int r = i >> 5;
        int c = (i & 31) * 4;
        float4 w4 = *(const float4*)&W[r * DIM + c];
        *(__half2*)&Ws[r][c]     = __floats2half2_rn(w4.x, w4.y);
        *(__half2*)&Ws[r][c + 2] = __floats2half2_rn(w4.z, w4.w);
    }

    float acc[16][4];
    #pragma unroll
    for (int i = 0; i < 16; i++)
        #pragma unroll
        for (int j = 0; j < 4; j++) acc[i][j] = 0.0f;

    for (int kc = 0; kc < 4; kc++) {
        int k0g = kc * 32;
        __syncthreads();             // As reuse fence (covers Ws on iter 0)
        if (FROM_GZ) {
            for (int i = tid; i < 512; i += 256) {
                int r = i >> 2;
                int c = (i & 3) * 8;
                int grow = rowBase + r;
                uint4 v = make_uint4(0u, 0u, 0u, 0u);
                if (grow < NN) v = *(const uint4*)&g_z16[(size_t)grow * DIM + k0g + c];
                *(uint4*)&As[r][c] = v;
            }
        } else {
            for (int i = tid; i < 1024; i += 256) {
                int r = i >> 3;
                int c = (i & 7) * 4;
                int grow = rowBase + r;
                float4 a4 = (grow < NN)
                    ? *(const float4*)&Ain[(size_t)grow * DIM + k0g + c]
                    : make_float4(0.f, 0.f, 0.f, 0.f);
                *(__half2*)&As[r][c]     = __floats2half2_rn(a4.x, a4.y);
                *(__half2*)&As[r][c + 2] = __floats2half2_rn(a4.z, a4.w);
            }
        }
        __syncthreads();

        #pragma unroll
        for (int ks = 0; ks < 2; ks++) {
            int k0 = ks * 16;
            int kg = k0g + k0;
            unsigned a0, a1, a2, a3;
            {
                unsigned addr = (unsigned)__cvta_generic_to_shared(
                    &As[m_base + (lane & 15)][k0 + ((lane >> 4) << 3)]);
                asm volatile("ldmatrix.sync.aligned.m8n8.x4.shared.b16 "
                             "{%0,%1,%2,%3}, [%4];"
                             : "=r"(a0), "=r"(a1), "=r"(a2), "=r"(a3) : "r"(addr));
            }
            #pragma unroll
            for (int nt = 0; nt < 8; nt++) {
                int n0 = nt * 16;
                unsigned b0, b1, b2, b3;
                unsigned addr = (unsigned)__cvta_generic_to_shared(
                    &Ws[kg + (lane & 15)][n0 + ((lane >> 4) << 3)]);
                asm volatile("ldmatrix.sync.aligned.m8n8.x4.trans.shared.b16 "
                             "{%0,%1,%2,%3}, [%4];"
                             : "=r"(b0), "=r"(b1), "=r"(b2), "=r"(b3) : "r"(addr));
                mma16816(acc[2 * nt],     a0, a1, a2, a3, b0, b1);
                mma16816(acc[2 * nt + 1], a0, a1, a2, a3, b2, b3);
            }
        }
    }

    // Epilogue: fp16 half2 stores into g_h
    int gq = lane >> 2, tg = lane & 3;
    int r0 = rowBase + m_base + gq;
    int r1 = r0 + 8;
    #pragma unroll
    for (int t8 = 0; t8 < 16; t8++) {
        int n0 = t8 * 8 + 2 * tg;
        if (r0 < NN) *(__half2*)&g_h[(size_t)r0 * DIM + n0] =
            __floats2half2_rn(acc[t8][0], acc[t8][1]);
        if (r1 < NN) *(__half2*)&g_h[(size_t)r1 * DIM + n0] =
            __floats2half2_rn(acc[t8][2], acc[t8][3]);
    }
}

// ---------------- aggregation: one warp per node, unroll-4 ----------------
__device__ __forceinline__ void gather_fma(float4 &acc, float n, uint2 raw) {
    float2 f01 = __half22float2(*(__half2*)&raw.x);
    float2 f23 = __half22float2(*(__half2*)&raw.y);
    acc.x += n * f01.x; acc.y += n * f01.y;
    acc.z += n * f23.x; acc.w += n * f23.y;
}

template<bool TO_OUT>
__global__ __launch_bounds__(128) void k_agg(const float* __restrict__ bias,
                                             float* __restrict__ outp) {
    int node = (blockIdx.x * blockDim.x + threadIdx.x) >> 5;
    int lane = threadIdx.x & 31;
    if (node >= NN) return;

    float di = g_dinv[node];
    float sn = di * di;              // self-loop norm (weight 1)

    const uint2* hrow = (const uint2*)(g_h + (size_t)node * DIM);
    float4 acc = make_float4(0.f, 0.f, 0.f, 0.f);
    gather_fma(acc, sn, hrow[lane]);

    int start = g_off[node];
    int cnt   = g_cnt[node];

    int e = 0;
    for (; e + 4 <= cnt; e += 4) {
        int2 E0 = g_edge[start + e];
        int2 E1 = g_edge[start + e + 1];
        int2 E2 = g_edge[start + e + 2];
        int2 E3 = g_edge[start + e + 3];
        uint2 V0 = ((const uint2*)(g_h + (size_t)E0.x * DIM))[lane];
        uint2 V1 = ((const uint2*)(g_h + (size_t)E1.x * DIM))[lane];
        uint2 V2 = ((const uint2*)(g_h + (size_t)E2.x * DIM))[lane];
        uint2 V3 = ((const uint2*)(g_h + (size_t)E3.x * DIM))[lane];
        gather_fma(acc, __int_as_float(E0.y), V0);
        gather_fma(acc, __int_as_float(E1.y), V1);
        gather_fma(acc, __int_as_float(E2.y), V2);
        gather_fma(acc, __int_as_float(E3.y), V3);
    }
    for (; e < cnt; e++) {
        int2 E0 = g_edge[start + e];
        uint2 V0 = ((const uint2*)(g_h + (size_t)E0.x * DIM))[lane];
        gather_fma(acc, __int_as_float(E0.y), V0);
    }

    float4 bb = ((const float4*)bias)[lane];
    acc.x = fmaxf(acc.x + bb.x, 0.0f);
    acc.y = fmaxf(acc.y + bb.y, 0.0f);
    acc.z = fmaxf(acc.z + bb.z, 0.0f);
    acc.w = fmaxf(acc.w + bb.w, 0.0f);

    if (TO_OUT) {
        ((float4*)outp)[(size_t)node * 32 + lane] = acc;
    } else {
        // fp16 store — numerically identical to fp32 store + fp16 load in gemm2
        __half2 p0 = __floats2half2_rn(acc.x, acc.y);
        __half2 p1 = __floats2half2_rn(acc.z, acc.w);
        uint2 v;
        v.x = *(unsigned*)&p0; v.y = *(unsigned*)&p1;
        *(uint2*)&g_z16[(size_t)node * DIM + lane * 4] = v;
    }
}

// ---------------- launch: fork-join build overlap, serial layers -----------
extern "C" void kernel_launch(void* const* d_in, const int* in_sizes, int n_in,
                              void* d_out, int out_size) {
    const float* x  = (const float*)d_in[0];
    const void*  ei = d_in[1];                    // int32 or int64 -> detected on device
    const float* ew = (const float*)d_in[2];
    const float* W1 = (const float*)d_in[3];
    const float* b1 = (const float*)d_in[4];
    const float* W2 = (const float*)d_in[5];
    const float* b2 = (const float*)d_in[6];
    float* out = (float*)d_out;

    const int gemm_grid = (NN + GEMM_BM - 1) / GEMM_BM;   // 782
    const int agg_grid  = (NN * 32 + 127) / 128;          // 25000
    const int pair_grid = (NE / 2 + 255) / 256;

    // one-time host objects (no device memory)
    static cudaStream_t s2 = nullptr;
    static cudaEvent_t  eFork = nullptr, eJoin = nullptr;
    if (!s2) {
        cudaStreamCreateWithFlags(&s2, cudaStreamNonBlocking);
        cudaEventCreateWithFlags(&eFork, cudaEventDisableTiming);
        cudaEventCreateWithFlags(&eJoin, cudaEventDisableTiming);
    }

    // fork: side stream builds CSC while main stream runs GEMM1
    cudaEventRecord(eFork, 0);
    cudaStreamWaitEvent(s2, eFork, 0);

    k_gemm<false><<<gemm_grid, 256>>>(x, W1);             // main: x @ W1 -> g_h

    k_init<<<(NN + 255) / 256, 256, 0, s2>>>((const int*)ei);
    k_hist<<<pair_grid, 256, 0, s2>>>(ei, ew);
    k_offsets<<<SCAN_NBLK, SCAN_B, 0, s2>>>();
    k_scatter<<<pair_grid, 256, 0, s2>>>(ei, ew);

    cudaEventRecord(eJoin, s2);
    cudaStreamWaitEvent(0, eJoin, 0);

    // --- layer 1 ---
    k_agg<false><<<agg_grid, 128>>>(b1, nullptr);         // -> g_z16

    // --- layer 2 ---
    k_gemm<true><<<gemm_grid, 256>>>(nullptr, W2);        // g_z16 @ W2 -> g_h
    k_agg<true><<<agg_grid, 128>>>(b2, out);
}